// round 11
// baseline (speedup 1.0000x reference)
#include <cuda_runtime.h>
#include <cuda_fp16.h>
#include <math.h>

#define N_NODES 200000
#define HDIM 8
#define FIN 64
#define PNODES 160  // nodes per proj block (200000 % 160 == 0)

// ---------------- packed parameter block (constant + staging) ----------------
struct CParams {               // field order == gather segment order (all float)
    float W[3][FIN * HDIM];    // 3 x 512
    float b[3][HDIM];
    float attSrc[4][HDIM];     // t0..t3
    float attDst[4][HDIM];
    float kW[HDIM * HDIM];
    float kb[HDIM];
    float q[HDIM];
    float linW[2][HDIM];
    float linB[2];
};
__constant__ CParams cP;
__device__ CParams gStage;

// ---------------- scratch (static device globals; no allocation) -------------
__device__ __align__(16) __half g_out[4 * (size_t)N_NODES * HDIM];  // zeroed by proj
__device__ __align__(16) float2 g_advden[4][(size_t)N_NODES];       // {ad, den} per type
__device__ __align__(16) __half g_hsrc[3][(size_t)N_NODES * HDIM];  // fp16 h per node type
__device__ float g_score[4];

__device__ __forceinline__ float fast_tanh(float x)
{
    float y;
    asm("tanh.approx.f32 %0, %1;" : "=f"(y) : "f"(x));
    return y;
}

// ---------------- parameter gather (one block) --------------------------------
struct SrcPtrs { const float* p[21]; };

__global__ void gather_kernel(SrcPtrs S)
{
    const int len[21] = {512,512,512, 8,8,8, 8,8,8,8, 8,8,8,8, 64,8,8, 8,8, 1,1};
    float* dst = reinterpret_cast<float*>(&gStage);
    int off = 0;
    for (int s = 0; s < 21; s++) {
        const float* src = S.p[s];
        for (int i = threadIdx.x; i < len[s]; i += blockDim.x)
            dst[off + i] = src[i];
        off += len[s];
    }
    if (threadIdx.x < 4) g_score[threadIdx.x] = 0.f;
}

// ---------------- fused projection (all 3 node types, grid.y) ----------------
// smem-staged coalesced loads; writes fp16 h row, {ad,0} pairs, zeroes out rows.
struct ProjCfg {
    const float* x[3];
    __half* hout[3];
    float2* advden0[3]; int adst0[3];   // dst alpha slot 0 (nullable)
    float2* advden1[3]; int adst1[3];   // dst alpha slot 1 (nullable)
    __half* zout0[3];                   // out array to zero (nullable)
    __half* zout1[3];
};

__global__ __launch_bounds__(PNODES) void proj_kernel(ProjCfg C)
{
    int ty = blockIdx.y;
    const float* x = C.x[ty];
    __shared__ float4 sx[PNODES * 17];   // stride-17 float4: conflict-free
    int tid = threadIdx.x;
    size_t base = (size_t)blockIdx.x * PNODES;

    const float4* xg = reinterpret_cast<const float4*>(x + base * FIN);
#pragma unroll 4
    for (int i = tid; i < PNODES * 16; i += PNODES) {
        int row = i >> 4, k4 = i & 15;
        sx[row * 17 + k4] = __ldcs(xg + i);
    }
    __syncthreads();

    const float* W = cP.W[ty];
    float acc[HDIM];
#pragma unroll
    for (int j = 0; j < HDIM; j++) acc[j] = cP.b[ty][j];
#pragma unroll
    for (int k4 = 0; k4 < 16; k4++) {
        float4 xv = sx[tid * 17 + k4];
#pragma unroll
        for (int j = 0; j < HDIM; j++) {
            acc[j] += xv.x * W[(4 * k4 + 0) * HDIM + j]
                    + xv.y * W[(4 * k4 + 1) * HDIM + j]
                    + xv.z * W[(4 * k4 + 2) * HDIM + j]
                    + xv.w * W[(4 * k4 + 3) * HDIM + j];
        }
    }

    size_t gn = base + tid;
    // fp16 h row (16B)
    __half2 hh[4];
#pragma unroll
    for (int i = 0; i < 4; i++) hh[i] = __floats2half2_rn(acc[2 * i], acc[2 * i + 1]);
    *reinterpret_cast<uint4*>(C.hout[ty] + gn * HDIM) = *reinterpret_cast<uint4*>(hh);

    if (C.advden0[ty]) {
        const float* att = cP.attDst[C.adst0[ty]];
        float v = 0.f;
#pragma unroll
        for (int j = 0; j < HDIM; j++) v += acc[j] * att[j];
        C.advden0[ty][gn] = make_float2(v, 0.f);
    }
    if (C.advden1[ty]) {
        const float* att = cP.attDst[C.adst1[ty]];
        float v = 0.f;
#pragma unroll
        for (int j = 0; j < HDIM; j++) v += acc[j] * att[j];
        C.advden1[ty][gn] = make_float2(v, 0.f);
    }
    // zero this dst node's accumulator rows (replaces global memset)
    uint4 z = make_uint4(0, 0, 0, 0);
    if (C.zout0[ty]) *reinterpret_cast<uint4*>(C.zout0[ty] + gn * HDIM) = z;
    if (C.zout1[ty]) *reinterpret_cast<uint4*>(C.zout1[ty] + gn * HDIM) = z;
}

// ---------------- fused edge pass (all 4 edge types, grid.y) -----------------
struct EdgeAll {
    const int*  ei[4];
    const __half* hsrc[4];
    float2* advden[4];
    __half* out[4];
    int E[4];
};

__device__ __forceinline__ void edge_one(int r, int c,
                                         const __half* __restrict__ hsrc,
                                         const float* __restrict__ attS,
                                         float2* __restrict__ advden,
                                         __half* __restrict__ out)
{
    uint4 hv = __ldg(reinterpret_cast<const uint4*>(hsrc + (size_t)r * HDIM)); // 8 fp16
    const __half2* hp = reinterpret_cast<const __half2*>(&hv);
    float2 f0 = __half22float2(hp[0]);
    float2 f1 = __half22float2(hp[1]);
    float2 f2 = __half22float2(hp[2]);
    float2 f3 = __half22float2(hp[3]);

    // recompute src alpha from gathered h (FMA pipe idle; saves a wavefront)
    float asv = f0.x * attS[0] + f0.y * attS[1]
              + f1.x * attS[2] + f1.y * attS[3]
              + f2.x * attS[4] + f2.y * attS[5]
              + f3.x * attS[6] + f3.y * attS[7];

    float a = asv + __ldg(&advden[c].x);
    a = (a > 0.f) ? a : 0.2f * a;
    float ex = __expf(a);

    // products in fp32, single rounding to fp16, one 16B vector red
    __half2 m0 = __floats2half2_rn(f0.x * ex, f0.y * ex);
    __half2 m1 = __floats2half2_rn(f1.x * ex, f1.y * ex);
    __half2 m2 = __floats2half2_rn(f2.x * ex, f2.y * ex);
    __half2 m3 = __floats2half2_rn(f3.x * ex, f3.y * ex);

    __half* op = out + (size_t)c * HDIM;
    asm volatile("red.global.add.noftz.v4.f16x2 [%0], {%1, %2, %3, %4};"
                 :: "l"(op),
                    "r"(*reinterpret_cast<unsigned*>(&m0)),
                    "r"(*reinterpret_cast<unsigned*>(&m1)),
                    "r"(*reinterpret_cast<unsigned*>(&m2)),
                    "r"(*reinterpret_cast<unsigned*>(&m3))
                 : "memory");
    atomicAdd(&advden[c].y, ex);   // same 8B pair as the ad load — hot line
}

__global__ void edge_kernel(EdgeAll A)
{
    int t = blockIdx.y;
    int E = A.E[t];
    const int*  ei  = A.ei[t];
    const __half* hsrc = A.hsrc[t];
    float2* advden = A.advden[t];
    __half* out = A.out[t];

    float attS[HDIM];
#pragma unroll
    for (int j = 0; j < HDIM; j++) attS[j] = cP.attSrc[t][j];

    int i0 = (blockIdx.x * blockDim.x + threadIdx.x) * 4;
    if (i0 + 4 <= E) {
        int4 rr = __ldcs(reinterpret_cast<const int4*>(ei + i0));
        int4 cc = __ldcs(reinterpret_cast<const int4*>(ei + E + i0));
        edge_one(rr.x, cc.x, hsrc, attS, advden, out);
        edge_one(rr.y, cc.y, hsrc, attS, advden, out);
        edge_one(rr.z, cc.z, hsrc, attS, advden, out);
        edge_one(rr.w, cc.w, hsrc, attS, advden, out);
    } else {
        for (int i = i0; i < E; i++)
            edge_one(ei[i], ei[E + i], hsrc, attS, advden, out);
    }
}

// ---------------- semantic score (all 4 metapaths, grid.y); inv inline -------
__global__ void score_kernel(const __half* __restrict__ out_base,
                             float* __restrict__ score)
{
    int g = blockIdx.y;
    const __half* o = out_base + (size_t)g * N_NODES * HDIM;
    int n = blockIdx.x * blockDim.x + threadIdx.x;
    float s = 0.f;
    if (n < N_NODES) {
        float2 adn = __ldg(&g_advden[g][n]);
        float inv = 1.f / (adn.y + 1e-16f);
        uint4 hv = __ldg(reinterpret_cast<const uint4*>(o + (size_t)n * HDIM));
        const __half2* hp = reinterpret_cast<const __half2*>(&hv);
        float2 f0 = __half22float2(hp[0]);
        float2 f1 = __half22float2(hp[1]);
        float2 f2 = __half22float2(hp[2]);
        float2 f3 = __half22float2(hp[3]);
        float orl[HDIM];
        orl[0] = fmaxf(f0.x * inv, 0.f); orl[1] = fmaxf(f0.y * inv, 0.f);
        orl[2] = fmaxf(f1.x * inv, 0.f); orl[3] = fmaxf(f1.y * inv, 0.f);
        orl[4] = fmaxf(f2.x * inv, 0.f); orl[5] = fmaxf(f2.y * inv, 0.f);
        orl[6] = fmaxf(f3.x * inv, 0.f); orl[7] = fmaxf(f3.y * inv, 0.f);
#pragma unroll
        for (int j = 0; j < HDIM; j++) {
            float acc = cP.kb[j];
#pragma unroll
            for (int k = 0; k < HDIM; k++) acc += orl[k] * cP.kW[k * HDIM + j];
            s += cP.q[j] * fast_tanh(acc);
        }
    }
#pragma unroll
    for (int off = 16; off; off >>= 1) s += __shfl_xor_sync(0xffffffffu, s, off);
    __shared__ float ws[8];
    int lane = threadIdx.x & 31, wid = threadIdx.x >> 5;
    if (lane == 0) ws[wid] = s;
    __syncthreads();
    if (wid == 0) {
        s = (lane < 8) ? ws[lane] : 0.f;
#pragma unroll
        for (int off = 4; off; off >>= 1) s += __shfl_xor_sync(0xffffffffu, s, off);
        if (lane == 0) atomicAdd(&score[g], s);
    }
}

// ---------------- final heads (both groups, grid.y); attn softmax inline -----
__global__ void final_kernel(const __half* __restrict__ out_base,
                             const float* __restrict__ score,
                             float* __restrict__ pred)
{
    int g = blockIdx.y;   // 0: ind (types 0,1), 1: org (types 2,3)
    int n = blockIdx.x * blockDim.x + threadIdx.x;
    if (n >= N_NODES) return;

    float s0 = __ldg(&score[2 * g])     * (1.f / (float)N_NODES);
    float s1 = __ldg(&score[2 * g + 1]) * (1.f / (float)N_NODES);
    float m  = fmaxf(s0, s1);
    float e0 = __expf(s0 - m), e1 = __expf(s1 - m);
    float winv = 1.f / (e0 + e1);
    float w0 = e0 * winv, w1 = e1 * winv;

    const __half* o0 = out_base + (size_t)(2 * g)     * N_NODES * HDIM;
    const __half* o1 = out_base + (size_t)(2 * g + 1) * N_NODES * HDIM;
    float i0 = 1.f / (__ldg(&g_advden[2 * g][n]).y     + 1e-16f);
    float i1 = 1.f / (__ldg(&g_advden[2 * g + 1][n]).y + 1e-16f);

    uint4 hv0 = __ldg(reinterpret_cast<const uint4*>(o0 + (size_t)n * HDIM));
    uint4 hv1 = __ldg(reinterpret_cast<const uint4*>(o1 + (size_t)n * HDIM));
    const __half2* hp0 = reinterpret_cast<const __half2*>(&hv0);
    const __half2* hp1 = reinterpret_cast<const __half2*>(&hv1);

    float s = cP.linB[g];
#pragma unroll
    for (int p = 0; p < 4; p++) {
        float2 a = __half22float2(hp0[p]);
        float2 b = __half22float2(hp1[p]);
        float z0 = w0 * fmaxf(a.x * i0, 0.f) + w1 * fmaxf(b.x * i1, 0.f);
        float z1 = w0 * fmaxf(a.y * i0, 0.f) + w1 * fmaxf(b.y * i1, 0.f);
        s += z0 * cP.linW[g][2 * p] + z1 * cP.linW[g][2 * p + 1];
    }
    pred[(size_t)g * N_NODES + n] = 1.f / (1.f + __expf(-s));
}

// -----------------------------------------------------------------------------
extern "C" void kernel_launch(void* const* d_in, const int* in_sizes, int n_in,
                              void* d_out, int out_size)
{
    __half *p_out, *p_h; float2* p_adv; float* p_score;
    cudaGetSymbolAddress((void**)&p_out, g_out);
    cudaGetSymbolAddress((void**)&p_h, g_hsrc);
    cudaGetSymbolAddress((void**)&p_adv, g_advden);
    cudaGetSymbolAddress((void**)&p_score, g_score);
    void *a_cP, *a_stage;
    cudaGetSymbolAddress(&a_cP, cP);
    cudaGetSymbolAddress(&a_stage, gStage);

    __half* h_ind = p_h;
    __half* h_org = p_h + (size_t)N_NODES * HDIM;
    __half* h_ext = p_h + 2 * (size_t)N_NODES * HDIM;
    float2* adv[4];
    __half* out_t[4];
    for (int t = 0; t < 4; t++) {
        adv[t]   = p_adv + (size_t)t * N_NODES;
        out_t[t] = p_out + (size_t)t * N_NODES * HDIM;
    }

    // ---- params: gather into staging, then ONE copy into constant bank ----
    SrcPtrs SP;
    SP.p[0]  = (const float*)d_in[7];   // W_ind
    SP.p[1]  = (const float*)d_in[9];   // W_org
    SP.p[2]  = (const float*)d_in[11];  // W_ext
    SP.p[3]  = (const float*)d_in[8];   // b_ind
    SP.p[4]  = (const float*)d_in[10];  // b_org
    SP.p[5]  = (const float*)d_in[12];  // b_ext
    // attSrc, edge types t0=org->ind, t1=ext->ind, t2=ind->org, t3=ext->org
    SP.p[6]  = (const float*)d_in[15];
    SP.p[7]  = (const float*)d_in[17];
    SP.p[8]  = (const float*)d_in[13];
    SP.p[9]  = (const float*)d_in[19];
    // attDst
    SP.p[10] = (const float*)d_in[16];
    SP.p[11] = (const float*)d_in[18];
    SP.p[12] = (const float*)d_in[14];
    SP.p[13] = (const float*)d_in[20];
    SP.p[14] = (const float*)d_in[21];  // kW
    SP.p[15] = (const float*)d_in[22];  // kb
    SP.p[16] = (const float*)d_in[23];  // q
    SP.p[17] = (const float*)d_in[24];  // lin_ind_W
    SP.p[18] = (const float*)d_in[26];  // lin_org_W
    SP.p[19] = (const float*)d_in[25];  // lin_ind_b
    SP.p[20] = (const float*)d_in[27];  // lin_org_b
    gather_kernel<<<1, 256>>>(SP);
    cudaMemcpyAsync(a_cP, a_stage, sizeof(CParams), cudaMemcpyDeviceToDevice, 0);

    // ---- projection (also zeroes advden.y and out rows — no memsets) ----
    ProjCfg PC;
    PC.x[0] = (const float*)d_in[0];  PC.hout[0] = h_ind;
    PC.x[1] = (const float*)d_in[1];  PC.hout[1] = h_org;
    PC.x[2] = (const float*)d_in[2];  PC.hout[2] = h_ext;
    // ind is dst of t0 (org->ind), t1 (ext->ind)
    PC.advden0[0] = adv[0]; PC.adst0[0] = 0;
    PC.advden1[0] = adv[1]; PC.adst1[0] = 1;
    PC.zout0[0] = out_t[0]; PC.zout1[0] = out_t[1];
    // org is dst of t2 (ind->org), t3 (ext->org)
    PC.advden0[1] = adv[2]; PC.adst0[1] = 2;
    PC.advden1[1] = adv[3]; PC.adst1[1] = 3;
    PC.zout0[1] = out_t[2]; PC.zout1[1] = out_t[3];
    // ext: src only
    PC.advden0[2] = nullptr; PC.adst0[2] = 0;
    PC.advden1[2] = nullptr; PC.adst1[2] = 0;
    PC.zout0[2] = nullptr;   PC.zout1[2] = nullptr;

    dim3 pg(N_NODES / PNODES, 3);
    proj_kernel<<<pg, PNODES>>>(PC);

    // ---- edges ----
    EdgeAll EA;
    EA.ei[0] = (const int*)d_in[4]; EA.E[0] = in_sizes[4] / 2; EA.hsrc[0] = h_org; // org->ind
    EA.ei[1] = (const int*)d_in[5]; EA.E[1] = in_sizes[5] / 2; EA.hsrc[1] = h_ext; // ext->ind
    EA.ei[2] = (const int*)d_in[3]; EA.E[2] = in_sizes[3] / 2; EA.hsrc[2] = h_ind; // ind->org
    EA.ei[3] = (const int*)d_in[6]; EA.E[3] = in_sizes[6] / 2; EA.hsrc[3] = h_ext; // ext->org
    int Emax = 0;
    for (int t = 0; t < 4; t++) {
        EA.advden[t] = adv[t];
        EA.out[t]    = out_t[t];
        if (EA.E[t] > Emax) Emax = EA.E[t];
    }
    dim3 eg((Emax / 4 + 255) / 256 + 1, 4);
    edge_kernel<<<eg, 256>>>(EA);

    // ---- semantic attention + heads ----
    const int NG = (N_NODES + 255) / 256;
    dim3 sg(NG, 4);
    score_kernel<<<sg, 256>>>(p_out, p_score);

    dim3 fg(NG, 2);
    final_kernel<<<fg, 256>>>(p_out, p_score, (float*)d_out);
}

// round 12
// speedup vs baseline: 1.0201x; 1.0201x over previous
#include <cuda_runtime.h>
#include <cuda_fp16.h>
#include <math.h>

#define N_NODES 200000
#define HDIM 8
#define FIN 64
#define PNODES 160  // nodes per proj block (200000 % 160 == 0)

// ---------------- packed parameter block (constant + staging) ----------------
struct CParams {               // field order == gather segment order (all float)
    float W[3][FIN * HDIM];    // 3 x 512
    float b[3][HDIM];
    float attSrc[4][HDIM];     // t0..t3
    float attDst[4][HDIM];
    float kW[HDIM * HDIM];
    float kb[HDIM];
    float q[HDIM];
    float linW[2][HDIM];
    float linB[2];
};
__constant__ CParams cP;
__device__ CParams gStage;

// ---------------- scratch (static device globals; no allocation) -------------
// out: 4*N*8 fp16 (12.8MB) followed by den: 4*N fp32 (3.2MB), one memset
#define OUT_BYTES (4 * (size_t)N_NODES * HDIM * 2)
#define DEN_BYTES (4 * (size_t)N_NODES * 4)
__device__ __align__(16) char g_accbuf[OUT_BYTES + DEN_BYTES];
__device__ __align__(16) __half g_hsrc[3][(size_t)N_NODES * HDIM]; // fp16 h per node type
__device__ float g_ad[4 * N_NODES];                 // per edge type: dst alpha (read-only in edge)
__device__ float g_score[4];

__device__ __forceinline__ float fast_tanh(float x)
{
    float y;
    asm("tanh.approx.f32 %0, %1;" : "=f"(y) : "f"(x));
    return y;
}

// h-row gather with evict-last L1 policy (hot 3.2MB array, random access)
__device__ __forceinline__ uint4 ldg_evict_last_v4(const void* p)
{
    uint4 v;
    asm volatile("ld.global.nc.L1::evict_last.v4.u32 {%0,%1,%2,%3}, [%4];"
                 : "=r"(v.x), "=r"(v.y), "=r"(v.z), "=r"(v.w) : "l"(p));
    return v;
}

// ---------------- parameter gather (one block) --------------------------------
struct SrcPtrs { const float* p[21]; };

__global__ void gather_kernel(SrcPtrs S)
{
    const int len[21] = {512,512,512, 8,8,8, 8,8,8,8, 8,8,8,8, 64,8,8, 8,8, 1,1};
    float* dst = reinterpret_cast<float*>(&gStage);
    int off = 0;
    for (int s = 0; s < 21; s++) {
        const float* src = S.p[s];
        for (int i = threadIdx.x; i < len[s]; i += blockDim.x)
            dst[off + i] = src[i];
        off += len[s];
    }
    if (threadIdx.x < 4) g_score[threadIdx.x] = 0.f;
}

// ---------------- fused projection (all 3 node types, grid.y) ----------------
struct ProjCfg {
    const float* x[3];
    __half* hout[3];
    float* ad0[3];  int adst0[3];
    float* ad1[3];  int adst1[3];
};

__global__ __launch_bounds__(PNODES) void proj_kernel(ProjCfg C)
{
    int ty = blockIdx.y;
    const float* x = C.x[ty];
    __shared__ float4 sx[PNODES * 17];   // stride-17 float4: conflict-free
    int tid = threadIdx.x;
    size_t base = (size_t)blockIdx.x * PNODES;

    const float4* xg = reinterpret_cast<const float4*>(x + base * FIN);
#pragma unroll 4
    for (int i = tid; i < PNODES * 16; i += PNODES) {
        int row = i >> 4, k4 = i & 15;
        sx[row * 17 + k4] = __ldcs(xg + i);
    }
    __syncthreads();

    const float* W = cP.W[ty];
    float acc[HDIM];
#pragma unroll
    for (int j = 0; j < HDIM; j++) acc[j] = cP.b[ty][j];
#pragma unroll
    for (int k4 = 0; k4 < 16; k4++) {
        float4 xv = sx[tid * 17 + k4];
#pragma unroll
        for (int j = 0; j < HDIM; j++) {
            acc[j] += xv.x * W[(4 * k4 + 0) * HDIM + j]
                    + xv.y * W[(4 * k4 + 1) * HDIM + j]
                    + xv.z * W[(4 * k4 + 2) * HDIM + j]
                    + xv.w * W[(4 * k4 + 3) * HDIM + j];
        }
    }

    size_t gn = base + tid;
    // fp16 h row (16B)
    __half2 hh[4];
#pragma unroll
    for (int i = 0; i < 4; i++) hh[i] = __floats2half2_rn(acc[2 * i], acc[2 * i + 1]);
    *reinterpret_cast<uint4*>(C.hout[ty] + gn * HDIM) = *reinterpret_cast<uint4*>(hh);

    if (C.ad0[ty]) {
        const float* att = cP.attDst[C.adst0[ty]];
        float v = 0.f;
#pragma unroll
        for (int j = 0; j < HDIM; j++) v += acc[j] * att[j];
        C.ad0[ty][gn] = v;
    }
    if (C.ad1[ty]) {
        const float* att = cP.attDst[C.adst1[ty]];
        float v = 0.f;
#pragma unroll
        for (int j = 0; j < HDIM; j++) v += acc[j] * att[j];
        C.ad1[ty][gn] = v;
    }
}

// ---------------- fused edge pass (all 4 edge types, grid.y) -----------------
struct EdgeAll {
    const int*  ei[4];
    const __half* hsrc[4];
    const float* ad[4];
    float* den[4];
    __half* out[4];
    int E[4];
};

__device__ __forceinline__ void edge_one(int r, int c,
                                         const __half* __restrict__ hsrc,
                                         const float* __restrict__ attS,
                                         const float* __restrict__ ad,
                                         float* __restrict__ den,
                                         __half* __restrict__ out)
{
    uint4 hv = ldg_evict_last_v4(hsrc + (size_t)r * HDIM);  // 8 fp16, L1 evict-last
    const __half2* hp = reinterpret_cast<const __half2*>(&hv);
    float2 f0 = __half22float2(hp[0]);
    float2 f1 = __half22float2(hp[1]);
    float2 f2 = __half22float2(hp[2]);
    float2 f3 = __half22float2(hp[3]);

    // recompute src alpha from gathered h (FMA pipe idle; saves a wavefront)
    float asv = f0.x * attS[0] + f0.y * attS[1]
              + f1.x * attS[2] + f1.y * attS[3]
              + f2.x * attS[4] + f2.y * attS[5]
              + f3.x * attS[6] + f3.y * attS[7];

    float a = asv + __ldg(&ad[c]);
    a = (a > 0.f) ? a : 0.2f * a;
    float ex = __expf(a);

    // products in fp32, single rounding to fp16, one 16B vector red
    __half2 m0 = __floats2half2_rn(f0.x * ex, f0.y * ex);
    __half2 m1 = __floats2half2_rn(f1.x * ex, f1.y * ex);
    __half2 m2 = __floats2half2_rn(f2.x * ex, f2.y * ex);
    __half2 m3 = __floats2half2_rn(f3.x * ex, f3.y * ex);

    __half* op = out + (size_t)c * HDIM;
    asm volatile("red.global.add.noftz.v4.f16x2 [%0], {%1, %2, %3, %4};"
                 :: "l"(op),
                    "r"(*reinterpret_cast<unsigned*>(&m0)),
                    "r"(*reinterpret_cast<unsigned*>(&m1)),
                    "r"(*reinterpret_cast<unsigned*>(&m2)),
                    "r"(*reinterpret_cast<unsigned*>(&m3))
                 : "memory");
    atomicAdd(&den[c], ex);
}

__global__ void edge_kernel(EdgeAll A)
{
    int t = blockIdx.y;
    int E = A.E[t];
    const int*  ei  = A.ei[t];
    const __half* hsrc = A.hsrc[t];
    const float* ad = A.ad[t];
    float* den = A.den[t];
    __half* out = A.out[t];

    float attS[HDIM];
#pragma unroll
    for (int j = 0; j < HDIM; j++) attS[j] = cP.attSrc[t][j];

    int i0 = (blockIdx.x * blockDim.x + threadIdx.x) * 4;
    if (i0 + 4 <= E) {
        int4 rr = __ldcs(reinterpret_cast<const int4*>(ei + i0));
        int4 cc = __ldcs(reinterpret_cast<const int4*>(ei + E + i0));
        edge_one(rr.x, cc.x, hsrc, attS, ad, den, out);
        edge_one(rr.y, cc.y, hsrc, attS, ad, den, out);
        edge_one(rr.z, cc.z, hsrc, attS, ad, den, out);
        edge_one(rr.w, cc.w, hsrc, attS, ad, den, out);
    } else {
        for (int i = i0; i < E; i++)
            edge_one(ei[i], ei[E + i], hsrc, attS, ad, den, out);
    }
}

// ---------------- semantic score (all 4 metapaths, grid.y); inv inline -------
__global__ void score_kernel(const __half* __restrict__ out_base,
                             const float* __restrict__ den_base,
                             float* __restrict__ score)
{
    int g = blockIdx.y;
    const __half* o = out_base + (size_t)g * N_NODES * HDIM;
    const float* den = den_base + (size_t)g * N_NODES;
    int n = blockIdx.x * blockDim.x + threadIdx.x;
    float s = 0.f;
    if (n < N_NODES) {
        float inv = 1.f / (__ldg(&den[n]) + 1e-16f);
        uint4 hv = __ldg(reinterpret_cast<const uint4*>(o + (size_t)n * HDIM));
        const __half2* hp = reinterpret_cast<const __half2*>(&hv);
        float2 f0 = __half22float2(hp[0]);
        float2 f1 = __half22float2(hp[1]);
        float2 f2 = __half22float2(hp[2]);
        float2 f3 = __half22float2(hp[3]);
        float orl[HDIM];
        orl[0] = fmaxf(f0.x * inv, 0.f); orl[1] = fmaxf(f0.y * inv, 0.f);
        orl[2] = fmaxf(f1.x * inv, 0.f); orl[3] = fmaxf(f1.y * inv, 0.f);
        orl[4] = fmaxf(f2.x * inv, 0.f); orl[5] = fmaxf(f2.y * inv, 0.f);
        orl[6] = fmaxf(f3.x * inv, 0.f); orl[7] = fmaxf(f3.y * inv, 0.f);
#pragma unroll
        for (int j = 0; j < HDIM; j++) {
            float acc = cP.kb[j];
#pragma unroll
            for (int k = 0; k < HDIM; k++) acc += orl[k] * cP.kW[k * HDIM + j];
            s += cP.q[j] * fast_tanh(acc);
        }
    }
#pragma unroll
    for (int off = 16; off; off >>= 1) s += __shfl_xor_sync(0xffffffffu, s, off);
    __shared__ float ws[8];
    int lane = threadIdx.x & 31, wid = threadIdx.x >> 5;
    if (lane == 0) ws[wid] = s;
    __syncthreads();
    if (wid == 0) {
        s = (lane < 8) ? ws[lane] : 0.f;
#pragma unroll
        for (int off = 4; off; off >>= 1) s += __shfl_xor_sync(0xffffffffu, s, off);
        if (lane == 0) atomicAdd(&score[g], s);
    }
}

// ---------------- final heads (both groups, grid.y); attn softmax inline -----
__global__ void final_kernel(const __half* __restrict__ out_base,
                             const float* __restrict__ den_base,
                             const float* __restrict__ score,
                             float* __restrict__ pred)
{
    int g = blockIdx.y;   // 0: ind (types 0,1), 1: org (types 2,3)
    int n = blockIdx.x * blockDim.x + threadIdx.x;
    if (n >= N_NODES) return;

    float s0 = __ldg(&score[2 * g])     * (1.f / (float)N_NODES);
    float s1 = __ldg(&score[2 * g + 1]) * (1.f / (float)N_NODES);
    float m  = fmaxf(s0, s1);
    float e0 = __expf(s0 - m), e1 = __expf(s1 - m);
    float winv = 1.f / (e0 + e1);
    float w0 = e0 * winv, w1 = e1 * winv;

    const __half* o0 = out_base + (size_t)(2 * g)     * N_NODES * HDIM;
    const __half* o1 = out_base + (size_t)(2 * g + 1) * N_NODES * HDIM;
    float i0 = 1.f / (__ldg(&den_base[(size_t)(2 * g)     * N_NODES + n]) + 1e-16f);
    float i1 = 1.f / (__ldg(&den_base[(size_t)(2 * g + 1) * N_NODES + n]) + 1e-16f);

    uint4 hv0 = __ldg(reinterpret_cast<const uint4*>(o0 + (size_t)n * HDIM));
    uint4 hv1 = __ldg(reinterpret_cast<const uint4*>(o1 + (size_t)n * HDIM));
    const __half2* hp0 = reinterpret_cast<const __half2*>(&hv0);
    const __half2* hp1 = reinterpret_cast<const __half2*>(&hv1);

    float s = cP.linB[g];
#pragma unroll
    for (int p = 0; p < 4; p++) {
        float2 a = __half22float2(hp0[p]);
        float2 b = __half22float2(hp1[p]);
        float z0 = w0 * fmaxf(a.x * i0, 0.f) + w1 * fmaxf(b.x * i1, 0.f);
        float z1 = w0 * fmaxf(a.y * i0, 0.f) + w1 * fmaxf(b.y * i1, 0.f);
        s += z0 * cP.linW[g][2 * p] + z1 * cP.linW[g][2 * p + 1];
    }
    pred[(size_t)g * N_NODES + n] = 1.f / (1.f + __expf(-s));
}

// -----------------------------------------------------------------------------
extern "C" void kernel_launch(void* const* d_in, const int* in_sizes, int n_in,
                              void* d_out, int out_size)
{
    char *p_accbuf; __half* p_h; float *p_ad, *p_score;
    cudaGetSymbolAddress((void**)&p_accbuf, g_accbuf);
    cudaGetSymbolAddress((void**)&p_h, g_hsrc);
    cudaGetSymbolAddress((void**)&p_ad, g_ad);
    cudaGetSymbolAddress((void**)&p_score, g_score);
    void *a_cP, *a_stage;
    cudaGetSymbolAddress(&a_cP, cP);
    cudaGetSymbolAddress(&a_stage, gStage);

    __half* p_out = reinterpret_cast<__half*>(p_accbuf);
    float*  p_den = reinterpret_cast<float*>(p_accbuf + OUT_BYTES);

    __half* h_ind = p_h;
    __half* h_org = p_h + (size_t)N_NODES * HDIM;
    __half* h_ext = p_h + 2 * (size_t)N_NODES * HDIM;

    // ---- params: gather into staging, then ONE copy into constant bank ----
    SrcPtrs SP;
    SP.p[0]  = (const float*)d_in[7];   // W_ind
    SP.p[1]  = (const float*)d_in[9];   // W_org
    SP.p[2]  = (const float*)d_in[11];  // W_ext
    SP.p[3]  = (const float*)d_in[8];   // b_ind
    SP.p[4]  = (const float*)d_in[10];  // b_org
    SP.p[5]  = (const float*)d_in[12];  // b_ext
    // attSrc, edge types t0=org->ind, t1=ext->ind, t2=ind->org, t3=ext->org
    SP.p[6]  = (const float*)d_in[15];
    SP.p[7]  = (const float*)d_in[17];
    SP.p[8]  = (const float*)d_in[13];
    SP.p[9]  = (const float*)d_in[19];
    // attDst
    SP.p[10] = (const float*)d_in[16];
    SP.p[11] = (const float*)d_in[18];
    SP.p[12] = (const float*)d_in[14];
    SP.p[13] = (const float*)d_in[20];
    SP.p[14] = (const float*)d_in[21];  // kW
    SP.p[15] = (const float*)d_in[22];  // kb
    SP.p[16] = (const float*)d_in[23];  // q
    SP.p[17] = (const float*)d_in[24];  // lin_ind_W
    SP.p[18] = (const float*)d_in[26];  // lin_org_W
    SP.p[19] = (const float*)d_in[25];  // lin_ind_b
    SP.p[20] = (const float*)d_in[27];  // lin_org_b
    gather_kernel<<<1, 256>>>(SP);
    cudaMemcpyAsync(a_cP, a_stage, sizeof(CParams), cudaMemcpyDeviceToDevice, 0);

    cudaMemsetAsync(p_accbuf, 0, OUT_BYTES + DEN_BYTES, 0);

    // ---- projection ----
    ProjCfg PC;
    PC.x[0] = (const float*)d_in[0];  PC.hout[0] = h_ind;
    PC.x[1] = (const float*)d_in[1];  PC.hout[1] = h_org;
    PC.x[2] = (const float*)d_in[2];  PC.hout[2] = h_ext;
    // ind: dst alphas for t0 (org->ind), t1 (ext->ind)
    PC.ad0[0] = p_ad + 0 * N_NODES; PC.adst0[0] = 0;
    PC.ad1[0] = p_ad + 1 * N_NODES; PC.adst1[0] = 1;
    // org: dst alphas for t2 (ind->org), t3 (ext->org)
    PC.ad0[1] = p_ad + 2 * N_NODES; PC.adst0[1] = 2;
    PC.ad1[1] = p_ad + 3 * N_NODES; PC.adst1[1] = 3;
    // ext: no dst alphas
    PC.ad0[2] = nullptr; PC.adst0[2] = 0;
    PC.ad1[2] = nullptr; PC.adst1[2] = 0;

    dim3 pg(N_NODES / PNODES, 3);
    proj_kernel<<<pg, PNODES>>>(PC);

    // ---- edges ----
    EdgeAll EA;
    EA.ei[0] = (const int*)d_in[4]; EA.E[0] = in_sizes[4] / 2; EA.hsrc[0] = h_org; // org->ind
    EA.ei[1] = (const int*)d_in[5]; EA.E[1] = in_sizes[5] / 2; EA.hsrc[1] = h_ext; // ext->ind
    EA.ei[2] = (const int*)d_in[3]; EA.E[2] = in_sizes[3] / 2; EA.hsrc[2] = h_ind; // ind->org
    EA.ei[3] = (const int*)d_in[6]; EA.E[3] = in_sizes[6] / 2; EA.hsrc[3] = h_ext; // ext->org
    int Emax = 0;
    for (int t = 0; t < 4; t++) {
        EA.ad[t]   = p_ad + (size_t)t * N_NODES;
        EA.den[t]  = p_den + (size_t)t * N_NODES;
        EA.out[t]  = p_out + (size_t)t * N_NODES * HDIM;
        if (EA.E[t] > Emax) Emax = EA.E[t];
    }
    dim3 eg((Emax / 4 + 255) / 256 + 1, 4);
    edge_kernel<<<eg, 256>>>(EA);

    // ---- semantic attention + heads ----
    const int NG = (N_NODES + 255) / 256;
    dim3 sg(NG, 4);
    score_kernel<<<sg, 256>>>(p_out, p_den, p_score);

    dim3 fg(NG, 2);
    final_kernel<<<fg, 256>>>(p_out, p_den, p_score, (float*)d_out);
}

// round 13
// speedup vs baseline: 1.0443x; 1.0237x over previous
#include <cuda_runtime.h>
#include <cuda_fp16.h>
#include <math.h>

#define N_NODES 200000
#define HDIM 8
#define FIN 64
#define PNODES 160  // nodes per proj block (200000 % 160 == 0)

// ---------------- packed parameter block (constant + staging) ----------------
struct CParams {               // field order == gather segment order (all float)
    float W[3][FIN * HDIM];    // 3 x 512
    float b[3][HDIM];
    float attSrc[4][HDIM];     // t0..t3
    float attDst[4][HDIM];
    float kW[HDIM * HDIM];
    float kb[HDIM];
    float q[HDIM];
    float linW[2][HDIM];
    float linB[2];
};
__constant__ CParams cP;
__device__ CParams gStage;

// ---------------- scratch (static device globals; no allocation) -------------
// out: 4*N*8 fp16 (12.8MB) followed by den: 4*N fp32 (3.2MB), one memset
#define OUT_BYTES (4 * (size_t)N_NODES * HDIM * 2)
#define DEN_BYTES (4 * (size_t)N_NODES * 4)
__device__ __align__(16) char g_accbuf[OUT_BYTES + DEN_BYTES];
__device__ __align__(16) __half g_hsrc[3][(size_t)N_NODES * HDIM]; // fp16 h per node type
__device__ float g_score[4];

__device__ __forceinline__ float fast_tanh(float x)
{
    float y;
    asm("tanh.approx.f32 %0, %1;" : "=f"(y) : "f"(x));
    return y;
}

// ---------------- parameter gather (one block) --------------------------------
struct SrcPtrs { const float* p[21]; };

__global__ void gather_kernel(SrcPtrs S)
{
    const int len[21] = {512,512,512, 8,8,8, 8,8,8,8, 8,8,8,8, 64,8,8, 8,8, 1,1};
    float* dst = reinterpret_cast<float*>(&gStage);
    int off = 0;
    for (int s = 0; s < 21; s++) {
        const float* src = S.p[s];
        for (int i = threadIdx.x; i < len[s]; i += blockDim.x)
            dst[off + i] = src[i];
        off += len[s];
    }
    if (threadIdx.x < 4) g_score[threadIdx.x] = 0.f;
}

// ---------------- fused projection (all 3 node types, grid.y) ----------------
// smem-staged coalesced loads; writes only the fp16 h row per node.
struct ProjCfg {
    const float* x[3];
    __half* hout[3];
};

__global__ __launch_bounds__(PNODES) void proj_kernel(ProjCfg C)
{
    int ty = blockIdx.y;
    const float* x = C.x[ty];
    __shared__ float4 sx[PNODES * 17];   // stride-17 float4: conflict-free
    int tid = threadIdx.x;
    size_t base = (size_t)blockIdx.x * PNODES;

    const float4* xg = reinterpret_cast<const float4*>(x + base * FIN);
#pragma unroll 4
    for (int i = tid; i < PNODES * 16; i += PNODES) {
        int row = i >> 4, k4 = i & 15;
        sx[row * 17 + k4] = __ldcs(xg + i);
    }
    __syncthreads();

    const float* W = cP.W[ty];
    float acc[HDIM];
#pragma unroll
    for (int j = 0; j < HDIM; j++) acc[j] = cP.b[ty][j];
#pragma unroll
    for (int k4 = 0; k4 < 16; k4++) {
        float4 xv = sx[tid * 17 + k4];
#pragma unroll
        for (int j = 0; j < HDIM; j++) {
            acc[j] += xv.x * W[(4 * k4 + 0) * HDIM + j]
                    + xv.y * W[(4 * k4 + 1) * HDIM + j]
                    + xv.z * W[(4 * k4 + 2) * HDIM + j]
                    + xv.w * W[(4 * k4 + 3) * HDIM + j];
        }
    }

    size_t gn = base + tid;
    __half2 hh[4];
#pragma unroll
    for (int i = 0; i < 4; i++) hh[i] = __floats2half2_rn(acc[2 * i], acc[2 * i + 1]);
    *reinterpret_cast<uint4*>(C.hout[ty] + gn * HDIM) = *reinterpret_cast<uint4*>(hh);
}

// ---------------- fused edge pass (all 4 edge types, grid.y) -----------------
// Both alphas recomputed from gathered fp16 h rows (src by r, dst by c).
struct EdgeAll {
    const int*  ei[4];
    const __half* hsrc[4];
    const __half* hdst[4];
    float* den[4];
    __half* out[4];
    int E[4];
};

__device__ __forceinline__ float dot8(const float2& f0, const float2& f1,
                                      const float2& f2, const float2& f3,
                                      const float* a)
{
    return f0.x * a[0] + f0.y * a[1] + f1.x * a[2] + f1.y * a[3]
         + f2.x * a[4] + f2.y * a[5] + f3.x * a[6] + f3.y * a[7];
}

__device__ __forceinline__ void edge_one(int r, int c,
                                         const __half* __restrict__ hsrc,
                                         const __half* __restrict__ hdst,
                                         const float* __restrict__ attS,
                                         const float* __restrict__ attD,
                                         float* __restrict__ den,
                                         __half* __restrict__ out)
{
    uint4 hv = __ldg(reinterpret_cast<const uint4*>(hsrc + (size_t)r * HDIM)); // src row
    uint4 dv = __ldg(reinterpret_cast<const uint4*>(hdst + (size_t)c * HDIM)); // dst row
    const __half2* hp = reinterpret_cast<const __half2*>(&hv);
    const __half2* dp = reinterpret_cast<const __half2*>(&dv);
    float2 f0 = __half22float2(hp[0]);
    float2 f1 = __half22float2(hp[1]);
    float2 f2 = __half22float2(hp[2]);
    float2 f3 = __half22float2(hp[3]);
    float2 g0 = __half22float2(dp[0]);
    float2 g1 = __half22float2(dp[1]);
    float2 g2 = __half22float2(dp[2]);
    float2 g3 = __half22float2(dp[3]);

    float a = dot8(f0, f1, f2, f3, attS) + dot8(g0, g1, g2, g3, attD);
    a = (a > 0.f) ? a : 0.2f * a;
    float ex = __expf(a);

    __half2 m0 = __floats2half2_rn(f0.x * ex, f0.y * ex);
    __half2 m1 = __floats2half2_rn(f1.x * ex, f1.y * ex);
    __half2 m2 = __floats2half2_rn(f2.x * ex, f2.y * ex);
    __half2 m3 = __floats2half2_rn(f3.x * ex, f3.y * ex);

    __half* op = out + (size_t)c * HDIM;
    asm volatile("red.global.add.noftz.v4.f16x2 [%0], {%1, %2, %3, %4};"
                 :: "l"(op),
                    "r"(*reinterpret_cast<unsigned*>(&m0)),
                    "r"(*reinterpret_cast<unsigned*>(&m1)),
                    "r"(*reinterpret_cast<unsigned*>(&m2)),
                    "r"(*reinterpret_cast<unsigned*>(&m3))
                 : "memory");
    atomicAdd(&den[c], ex);
}

__global__ void edge_kernel(EdgeAll A)
{
    int t = blockIdx.y;
    int E = A.E[t];
    const int*  ei  = A.ei[t];
    const __half* hsrc = A.hsrc[t];
    const __half* hdst = A.hdst[t];
    float* den = A.den[t];
    __half* out = A.out[t];

    float attS[HDIM], attD[HDIM];
#pragma unroll
    for (int j = 0; j < HDIM; j++) { attS[j] = cP.attSrc[t][j]; attD[j] = cP.attDst[t][j]; }

    int i0 = (blockIdx.x * blockDim.x + threadIdx.x) * 4;
    if (i0 + 4 <= E) {
        int4 rr = __ldcs(reinterpret_cast<const int4*>(ei + i0));
        int4 cc = __ldcs(reinterpret_cast<const int4*>(ei + E + i0));
        edge_one(rr.x, cc.x, hsrc, hdst, attS, attD, den, out);
        edge_one(rr.y, cc.y, hsrc, hdst, attS, attD, den, out);
        edge_one(rr.z, cc.z, hsrc, hdst, attS, attD, den, out);
        edge_one(rr.w, cc.w, hsrc, hdst, attS, attD, den, out);
    } else {
        for (int i = i0; i < E; i++)
            edge_one(ei[i], ei[E + i], hsrc, hdst, attS, attD, den, out);
    }
}

// ---------------- semantic score (all 4 metapaths, grid.y); inv inline -------
__global__ void score_kernel(const __half* __restrict__ out_base,
                             const float* __restrict__ den_base,
                             float* __restrict__ score)
{
    int g = blockIdx.y;
    const __half* o = out_base + (size_t)g * N_NODES * HDIM;
    const float* den = den_base + (size_t)g * N_NODES;
    int n = blockIdx.x * blockDim.x + threadIdx.x;
    float s = 0.f;
    if (n < N_NODES) {
        float inv = 1.f / (__ldg(&den[n]) + 1e-16f);
        uint4 hv = __ldg(reinterpret_cast<const uint4*>(o + (size_t)n * HDIM));
        const __half2* hp = reinterpret_cast<const __half2*>(&hv);
        float2 f0 = __half22float2(hp[0]);
        float2 f1 = __half22float2(hp[1]);
        float2 f2 = __half22float2(hp[2]);
        float2 f3 = __half22float2(hp[3]);
        float orl[HDIM];
        orl[0] = fmaxf(f0.x * inv, 0.f); orl[1] = fmaxf(f0.y * inv, 0.f);
        orl[2] = fmaxf(f1.x * inv, 0.f); orl[3] = fmaxf(f1.y * inv, 0.f);
        orl[4] = fmaxf(f2.x * inv, 0.f); orl[5] = fmaxf(f2.y * inv, 0.f);
        orl[6] = fmaxf(f3.x * inv, 0.f); orl[7] = fmaxf(f3.y * inv, 0.f);
#pragma unroll
        for (int j = 0; j < HDIM; j++) {
            float acc = cP.kb[j];
#pragma unroll
            for (int k = 0; k < HDIM; k++) acc += orl[k] * cP.kW[k * HDIM + j];
            s += cP.q[j] * fast_tanh(acc);
        }
    }
#pragma unroll
    for (int off = 16; off; off >>= 1) s += __shfl_xor_sync(0xffffffffu, s, off);
    __shared__ float ws[8];
    int lane = threadIdx.x & 31, wid = threadIdx.x >> 5;
    if (lane == 0) ws[wid] = s;
    __syncthreads();
    if (wid == 0) {
        s = (lane < 8) ? ws[lane] : 0.f;
#pragma unroll
        for (int off = 4; off; off >>= 1) s += __shfl_xor_sync(0xffffffffu, s, off);
        if (lane == 0) atomicAdd(&score[g], s);
    }
}

// ---------------- final heads (both groups, grid.y); attn softmax inline -----
__global__ void final_kernel(const __half* __restrict__ out_base,
                             const float* __restrict__ den_base,
                             const float* __restrict__ score,
                             float* __restrict__ pred)
{
    int g = blockIdx.y;   // 0: ind (types 0,1), 1: org (types 2,3)
    int n = blockIdx.x * blockDim.x + threadIdx.x;
    if (n >= N_NODES) return;

    float s0 = __ldg(&score[2 * g])     * (1.f / (float)N_NODES);
    float s1 = __ldg(&score[2 * g + 1]) * (1.f / (float)N_NODES);
    float m  = fmaxf(s0, s1);
    float e0 = __expf(s0 - m), e1 = __expf(s1 - m);
    float winv = 1.f / (e0 + e1);
    float w0 = e0 * winv, w1 = e1 * winv;

    const __half* o0 = out_base + (size_t)(2 * g)     * N_NODES * HDIM;
    const __half* o1 = out_base + (size_t)(2 * g + 1) * N_NODES * HDIM;
    float i0 = 1.f / (__ldg(&den_base[(size_t)(2 * g)     * N_NODES + n]) + 1e-16f);
    float i1 = 1.f / (__ldg(&den_base[(size_t)(2 * g + 1) * N_NODES + n]) + 1e-16f);

    uint4 hv0 = __ldg(reinterpret_cast<const uint4*>(o0 + (size_t)n * HDIM));
    uint4 hv1 = __ldg(reinterpret_cast<const uint4*>(o1 + (size_t)n * HDIM));
    const __half2* hp0 = reinterpret_cast<const __half2*>(&hv0);
    const __half2* hp1 = reinterpret_cast<const __half2*>(&hv1);

    float s = cP.linB[g];
#pragma unroll
    for (int p = 0; p < 4; p++) {
        float2 a = __half22float2(hp0[p]);
        float2 b = __half22float2(hp1[p]);
        float z0 = w0 * fmaxf(a.x * i0, 0.f) + w1 * fmaxf(b.x * i1, 0.f);
        float z1 = w0 * fmaxf(a.y * i0, 0.f) + w1 * fmaxf(b.y * i1, 0.f);
        s += z0 * cP.linW[g][2 * p] + z1 * cP.linW[g][2 * p + 1];
    }
    pred[(size_t)g * N_NODES + n] = 1.f / (1.f + __expf(-s));
}

// -----------------------------------------------------------------------------
extern "C" void kernel_launch(void* const* d_in, const int* in_sizes, int n_in,
                              void* d_out, int out_size)
{
    char *p_accbuf; __half* p_h; float* p_score;
    cudaGetSymbolAddress((void**)&p_accbuf, g_accbuf);
    cudaGetSymbolAddress((void**)&p_h, g_hsrc);
    cudaGetSymbolAddress((void**)&p_score, g_score);
    void *a_cP, *a_stage;
    cudaGetSymbolAddress(&a_cP, cP);
    cudaGetSymbolAddress(&a_stage, gStage);

    __half* p_out = reinterpret_cast<__half*>(p_accbuf);
    float*  p_den = reinterpret_cast<float*>(p_accbuf + OUT_BYTES);

    __half* h_ind = p_h;
    __half* h_org = p_h + (size_t)N_NODES * HDIM;
    __half* h_ext = p_h + 2 * (size_t)N_NODES * HDIM;

    // ---- params: gather into staging, then ONE copy into constant bank ----
    SrcPtrs SP;
    SP.p[0]  = (const float*)d_in[7];   // W_ind
    SP.p[1]  = (const float*)d_in[9];   // W_org
    SP.p[2]  = (const float*)d_in[11];  // W_ext
    SP.p[3]  = (const float*)d_in[8];   // b_ind
    SP.p[4]  = (const float*)d_in[10];  // b_org
    SP.p[5]  = (const float*)d_in[12];  // b_ext
    // attSrc, edge types t0=org->ind, t1=ext->ind, t2=ind->org, t3=ext->org
    SP.p[6]  = (const float*)d_in[15];
    SP.p[7]  = (const float*)d_in[17];
    SP.p[8]  = (const float*)d_in[13];
    SP.p[9]  = (const float*)d_in[19];
    // attDst
    SP.p[10] = (const float*)d_in[16];
    SP.p[11] = (const float*)d_in[18];
    SP.p[12] = (const float*)d_in[14];
    SP.p[13] = (const float*)d_in[20];
    SP.p[14] = (const float*)d_in[21];  // kW
    SP.p[15] = (const float*)d_in[22];  // kb
    SP.p[16] = (const float*)d_in[23];  // q
    SP.p[17] = (const float*)d_in[24];  // lin_ind_W
    SP.p[18] = (const float*)d_in[26];  // lin_org_W
    SP.p[19] = (const float*)d_in[25];  // lin_ind_b
    SP.p[20] = (const float*)d_in[27];  // lin_org_b
    gather_kernel<<<1, 256>>>(SP);
    cudaMemcpyAsync(a_cP, a_stage, sizeof(CParams), cudaMemcpyDeviceToDevice, 0);

    cudaMemsetAsync(p_accbuf, 0, OUT_BYTES + DEN_BYTES, 0);

    // ---- projection (h rows only) ----
    ProjCfg PC;
    PC.x[0] = (const float*)d_in[0];  PC.hout[0] = h_ind;
    PC.x[1] = (const float*)d_in[1];  PC.hout[1] = h_org;
    PC.x[2] = (const float*)d_in[2];  PC.hout[2] = h_ext;

    dim3 pg(N_NODES / PNODES, 3);
    proj_kernel<<<pg, PNODES>>>(PC);

    // ---- edges ----
    EdgeAll EA;
    EA.ei[0] = (const int*)d_in[4]; EA.E[0] = in_sizes[4] / 2; EA.hsrc[0] = h_org; EA.hdst[0] = h_ind; // org->ind
    EA.ei[1] = (const int*)d_in[5]; EA.E[1] = in_sizes[5] / 2; EA.hsrc[1] = h_ext; EA.hdst[1] = h_ind; // ext->ind
    EA.ei[2] = (const int*)d_in[3]; EA.E[2] = in_sizes[3] / 2; EA.hsrc[2] = h_ind; EA.hdst[2] = h_org; // ind->org
    EA.ei[3] = (const int*)d_in[6]; EA.E[3] = in_sizes[6] / 2; EA.hsrc[3] = h_ext; EA.hdst[3] = h_org; // ext->org
    int Emax = 0;
    for (int t = 0; t < 4; t++) {
        EA.den[t]  = p_den + (size_t)t * N_NODES;
        EA.out[t]  = p_out + (size_t)t * N_NODES * HDIM;
        if (EA.E[t] > Emax) Emax = EA.E[t];
    }
    dim3 eg((Emax / 4 + 255) / 256 + 1, 4);
    edge_kernel<<<eg, 256>>>(EA);

    // ---- semantic attention + heads ----
    const int NG = (N_NODES + 255) / 256;
    dim3 sg(NG, 4);
    score_kernel<<<sg, 256>>>(p_out, p_den, p_score);

    dim3 fg(NG, 2);
    final_kernel<<<fg, 256>>>(p_out, p_den, p_score, (float*)d_out);
}

// round 14
// speedup vs baseline: 1.0450x; 1.0007x over previous
#include <cuda_runtime.h>
#include <cuda_fp16.h>
#include <math.h>

#define N_NODES 200000
#define HDIM 8
#define FIN 64
#define PNODES 160  // nodes per proj block (200000 % 160 == 0)

// ---------------- packed parameter block (constant + staging) ----------------
struct CParams {               // field order == gather segment order (all float)
    float W[3][FIN * HDIM];    // 3 x 512
    float b[3][HDIM];
    float attSrc[4][HDIM];     // t0..t3
    float attDst[4][HDIM];
    float kW[HDIM * HDIM];
    float kb[HDIM];
    float q[HDIM];
    float linW[2][HDIM];
    float linB[2];
};
__constant__ CParams cP;
__device__ CParams gStage;

// ---------------- scratch (static device globals; no allocation) -------------
// out: 4*N*8 fp16 (12.8MB) followed by den: 4*N fp32 (3.2MB), one memset
#define OUT_BYTES (4 * (size_t)N_NODES * HDIM * 2)
#define DEN_BYTES (4 * (size_t)N_NODES * 4)
__device__ __align__(16) char g_accbuf[OUT_BYTES + DEN_BYTES];
__device__ __align__(16) __half g_hsrc[3][(size_t)N_NODES * HDIM]; // fp16 h per node type
__device__ float g_A[4][(size_t)N_NODES];  // per-metapath A[n] = relu(o*inv)·linW
__device__ float g_score[4];

__device__ __forceinline__ float fast_tanh(float x)
{
    float y;
    asm("tanh.approx.f32 %0, %1;" : "=f"(y) : "f"(x));
    return y;
}

// ---------------- parameter gather (one block) --------------------------------
struct SrcPtrs { const float* p[21]; };

__global__ void gather_kernel(SrcPtrs S)
{
    const int len[21] = {512,512,512, 8,8,8, 8,8,8,8, 8,8,8,8, 64,8,8, 8,8, 1,1};
    float* dst = reinterpret_cast<float*>(&gStage);
    int off = 0;
    for (int s = 0; s < 21; s++) {
        const float* src = S.p[s];
        for (int i = threadIdx.x; i < len[s]; i += blockDim.x)
            dst[off + i] = src[i];
        off += len[s];
    }
    if (threadIdx.x < 4) g_score[threadIdx.x] = 0.f;
}

// ---------------- fused projection (all 3 node types, grid.y) ----------------
struct ProjCfg {
    const float* x[3];
    __half* hout[3];
};

__global__ __launch_bounds__(PNODES) void proj_kernel(ProjCfg C)
{
    int ty = blockIdx.y;
    const float* x = C.x[ty];
    __shared__ float4 sx[PNODES * 17];   // stride-17 float4: conflict-free
    int tid = threadIdx.x;
    size_t base = (size_t)blockIdx.x * PNODES;

    const float4* xg = reinterpret_cast<const float4*>(x + base * FIN);
#pragma unroll 4
    for (int i = tid; i < PNODES * 16; i += PNODES) {
        int row = i >> 4, k4 = i & 15;
        sx[row * 17 + k4] = __ldcs(xg + i);
    }
    __syncthreads();

    const float* W = cP.W[ty];
    float acc[HDIM];
#pragma unroll
    for (int j = 0; j < HDIM; j++) acc[j] = cP.b[ty][j];
#pragma unroll
    for (int k4 = 0; k4 < 16; k4++) {
        float4 xv = sx[tid * 17 + k4];
#pragma unroll
        for (int j = 0; j < HDIM; j++) {
            acc[j] += xv.x * W[(4 * k4 + 0) * HDIM + j]
                    + xv.y * W[(4 * k4 + 1) * HDIM + j]
                    + xv.z * W[(4 * k4 + 2) * HDIM + j]
                    + xv.w * W[(4 * k4 + 3) * HDIM + j];
        }
    }

    size_t gn = base + tid;
    __half2 hh[4];
#pragma unroll
    for (int i = 0; i < 4; i++) hh[i] = __floats2half2_rn(acc[2 * i], acc[2 * i + 1]);
    *reinterpret_cast<uint4*>(C.hout[ty] + gn * HDIM) = *reinterpret_cast<uint4*>(hh);
}

// ---------------- fused edge pass (all 4 edge types, grid.y) -----------------
struct EdgeAll {
    const int*  ei[4];
    const __half* hsrc[4];
    const __half* hdst[4];
    float* den[4];
    __half* out[4];
    int E[4];
};

__device__ __forceinline__ float dot8(const float2& f0, const float2& f1,
                                      const float2& f2, const float2& f3,
                                      const float* a)
{
    return f0.x * a[0] + f0.y * a[1] + f1.x * a[2] + f1.y * a[3]
         + f2.x * a[4] + f2.y * a[5] + f3.x * a[6] + f3.y * a[7];
}

__device__ __forceinline__ void edge_one(int r, int c,
                                         const __half* __restrict__ hsrc,
                                         const __half* __restrict__ hdst,
                                         const float* __restrict__ attS,
                                         const float* __restrict__ attD,
                                         float* __restrict__ den,
                                         __half* __restrict__ out)
{
    uint4 hv = __ldg(reinterpret_cast<const uint4*>(hsrc + (size_t)r * HDIM)); // src row
    uint4 dv = __ldg(reinterpret_cast<const uint4*>(hdst + (size_t)c * HDIM)); // dst row
    const __half2* hp = reinterpret_cast<const __half2*>(&hv);
    const __half2* dp = reinterpret_cast<const __half2*>(&dv);
    float2 f0 = __half22float2(hp[0]);
    float2 f1 = __half22float2(hp[1]);
    float2 f2 = __half22float2(hp[2]);
    float2 f3 = __half22float2(hp[3]);
    float2 g0 = __half22float2(dp[0]);
    float2 g1 = __half22float2(dp[1]);
    float2 g2 = __half22float2(dp[2]);
    float2 g3 = __half22float2(dp[3]);

    float a = dot8(f0, f1, f2, f3, attS) + dot8(g0, g1, g2, g3, attD);
    a = (a > 0.f) ? a : 0.2f * a;
    float ex = __expf(a);

    __half2 m0 = __floats2half2_rn(f0.x * ex, f0.y * ex);
    __half2 m1 = __floats2half2_rn(f1.x * ex, f1.y * ex);
    __half2 m2 = __floats2half2_rn(f2.x * ex, f2.y * ex);
    __half2 m3 = __floats2half2_rn(f3.x * ex, f3.y * ex);

    __half* op = out + (size_t)c * HDIM;
    asm volatile("red.global.add.noftz.v4.f16x2 [%0], {%1, %2, %3, %4};"
                 :: "l"(op),
                    "r"(*reinterpret_cast<unsigned*>(&m0)),
                    "r"(*reinterpret_cast<unsigned*>(&m1)),
                    "r"(*reinterpret_cast<unsigned*>(&m2)),
                    "r"(*reinterpret_cast<unsigned*>(&m3))
                 : "memory");
    atomicAdd(&den[c], ex);
}

__global__ void edge_kernel(EdgeAll A)
{
    int t = blockIdx.y;
    int E = A.E[t];
    const int*  ei  = A.ei[t];
    const __half* hsrc = A.hsrc[t];
    const __half* hdst = A.hdst[t];
    float* den = A.den[t];
    __half* out = A.out[t];

    float attS[HDIM], attD[HDIM];
#pragma unroll
    for (int j = 0; j < HDIM; j++) { attS[j] = cP.attSrc[t][j]; attD[j] = cP.attDst[t][j]; }

    int i0 = (blockIdx.x * blockDim.x + threadIdx.x) * 4;
    if (i0 + 4 <= E) {
        int4 rr = __ldcs(reinterpret_cast<const int4*>(ei + i0));
        int4 cc = __ldcs(reinterpret_cast<const int4*>(ei + E + i0));
        edge_one(rr.x, cc.x, hsrc, hdst, attS, attD, den, out);
        edge_one(rr.y, cc.y, hsrc, hdst, attS, attD, den, out);
        edge_one(rr.z, cc.z, hsrc, hdst, attS, attD, den, out);
        edge_one(rr.w, cc.w, hsrc, hdst, attS, attD, den, out);
    } else {
        for (int i = i0; i < E; i++)
            edge_one(ei[i], ei[E + i], hsrc, hdst, attS, attD, den, out);
    }
}

// ---------------- semantic score + per-node head dot (all 4 metapaths) -------
// Emits score_g (global reduction) AND A_g[n] = relu(o*inv)·linW[g/2].
__global__ void score_kernel(const __half* __restrict__ out_base,
                             const float* __restrict__ den_base,
                             float* __restrict__ score)
{
    int g = blockIdx.y;
    const __half* o = out_base + (size_t)g * N_NODES * HDIM;
    const float* den = den_base + (size_t)g * N_NODES;
    int n = blockIdx.x * blockDim.x + threadIdx.x;
    float s = 0.f;
    if (n < N_NODES) {
        float inv = 1.f / (__ldg(&den[n]) + 1e-16f);
        uint4 hv = __ldg(reinterpret_cast<const uint4*>(o + (size_t)n * HDIM));
        const __half2* hp = reinterpret_cast<const __half2*>(&hv);
        float2 f0 = __half22float2(hp[0]);
        float2 f1 = __half22float2(hp[1]);
        float2 f2 = __half22float2(hp[2]);
        float2 f3 = __half22float2(hp[3]);
        float orl[HDIM];
        orl[0] = fmaxf(f0.x * inv, 0.f); orl[1] = fmaxf(f0.y * inv, 0.f);
        orl[2] = fmaxf(f1.x * inv, 0.f); orl[3] = fmaxf(f1.y * inv, 0.f);
        orl[4] = fmaxf(f2.x * inv, 0.f); orl[5] = fmaxf(f2.y * inv, 0.f);
        orl[6] = fmaxf(f3.x * inv, 0.f); orl[7] = fmaxf(f3.y * inv, 0.f);

        // per-node head dot for the final sigmoid (linW of this group)
        const float* lw = cP.linW[g >> 1];
        float A = 0.f;
#pragma unroll
        for (int j = 0; j < HDIM; j++) A += orl[j] * lw[j];
        g_A[g][n] = A;

#pragma unroll
        for (int j = 0; j < HDIM; j++) {
            float acc = cP.kb[j];
#pragma unroll
            for (int k = 0; k < HDIM; k++) acc += orl[k] * cP.kW[k * HDIM + j];
            s += cP.q[j] * fast_tanh(acc);
        }
    }
#pragma unroll
    for (int off = 16; off; off >>= 1) s += __shfl_xor_sync(0xffffffffu, s, off);
    __shared__ float ws[8];
    int lane = threadIdx.x & 31, wid = threadIdx.x >> 5;
    if (lane == 0) ws[wid] = s;
    __syncthreads();
    if (wid == 0) {
        s = (lane < 8) ? ws[lane] : 0.f;
#pragma unroll
        for (int off = 4; off; off >>= 1) s += __shfl_xor_sync(0xffffffffu, s, off);
        if (lane == 0) atomicAdd(&score[g], s);
    }
}

// ---------------- final heads: tiny pass over A arrays -----------------------
__global__ void final_kernel(const float* __restrict__ score,
                             float* __restrict__ pred)
{
    int n = blockIdx.x * blockDim.x + threadIdx.x;
    if (n >= N_NODES) return;

    // both groups' softmax weights (uniform; cheap per thread)
    float w[4];
#pragma unroll
    for (int g = 0; g < 2; g++) {
        float s0 = __ldg(&score[2 * g])     * (1.f / (float)N_NODES);
        float s1 = __ldg(&score[2 * g + 1]) * (1.f / (float)N_NODES);
        float m  = fmaxf(s0, s1);
        float e0 = __expf(s0 - m), e1 = __expf(s1 - m);
        float winv = 1.f / (e0 + e1);
        w[2 * g] = e0 * winv; w[2 * g + 1] = e1 * winv;
    }

    float a0 = __ldg(&g_A[0][n]);
    float a1 = __ldg(&g_A[1][n]);
    float a2 = __ldg(&g_A[2][n]);
    float a3 = __ldg(&g_A[3][n]);

    float sInd = cP.linB[0] + w[0] * a0 + w[1] * a1;
    float sOrg = cP.linB[1] + w[2] * a2 + w[3] * a3;
    pred[n]           = 1.f / (1.f + __expf(-sInd));
    pred[N_NODES + n] = 1.f / (1.f + __expf(-sOrg));
}

// -----------------------------------------------------------------------------
extern "C" void kernel_launch(void* const* d_in, const int* in_sizes, int n_in,
                              void* d_out, int out_size)
{
    char *p_accbuf; __half* p_h; float* p_score;
    cudaGetSymbolAddress((void**)&p_accbuf, g_accbuf);
    cudaGetSymbolAddress((void**)&p_h, g_hsrc);
    cudaGetSymbolAddress((void**)&p_score, g_score);
    void *a_cP, *a_stage;
    cudaGetSymbolAddress(&a_cP, cP);
    cudaGetSymbolAddress(&a_stage, gStage);

    __half* p_out = reinterpret_cast<__half*>(p_accbuf);
    float*  p_den = reinterpret_cast<float*>(p_accbuf + OUT_BYTES);

    __half* h_ind = p_h;
    __half* h_org = p_h + (size_t)N_NODES * HDIM;
    __half* h_ext = p_h + 2 * (size_t)N_NODES * HDIM;

    // ---- params: gather into staging, then ONE copy into constant bank ----
    SrcPtrs SP;
    SP.p[0]  = (const float*)d_in[7];   // W_ind
    SP.p[1]  = (const float*)d_in[9];   // W_org
    SP.p[2]  = (const float*)d_in[11];  // W_ext
    SP.p[3]  = (const float*)d_in[8];   // b_ind
    SP.p[4]  = (const float*)d_in[10];  // b_org
    SP.p[5]  = (const float*)d_in[12];  // b_ext
    // attSrc, edge types t0=org->ind, t1=ext->ind, t2=ind->org, t3=ext->org
    SP.p[6]  = (const float*)d_in[15];
    SP.p[7]  = (const float*)d_in[17];
    SP.p[8]  = (const float*)d_in[13];
    SP.p[9]  = (const float*)d_in[19];
    // attDst
    SP.p[10] = (const float*)d_in[16];
    SP.p[11] = (const float*)d_in[18];
    SP.p[12] = (const float*)d_in[14];
    SP.p[13] = (const float*)d_in[20];
    SP.p[14] = (const float*)d_in[21];  // kW
    SP.p[15] = (const float*)d_in[22];  // kb
    SP.p[16] = (const float*)d_in[23];  // q
    SP.p[17] = (const float*)d_in[24];  // lin_ind_W
    SP.p[18] = (const float*)d_in[26];  // lin_org_W
    SP.p[19] = (const float*)d_in[25];  // lin_ind_b
    SP.p[20] = (const float*)d_in[27];  // lin_org_b
    gather_kernel<<<1, 256>>>(SP);
    cudaMemcpyAsync(a_cP, a_stage, sizeof(CParams), cudaMemcpyDeviceToDevice, 0);

    cudaMemsetAsync(p_accbuf, 0, OUT_BYTES + DEN_BYTES, 0);

    // ---- projection (h rows only) ----
    ProjCfg PC;
    PC.x[0] = (const float*)d_in[0];  PC.hout[0] = h_ind;
    PC.x[1] = (const float*)d_in[1];  PC.hout[1] = h_org;
    PC.x[2] = (const float*)d_in[2];  PC.hout[2] = h_ext;

    dim3 pg(N_NODES / PNODES, 3);
    proj_kernel<<<pg, PNODES>>>(PC);

    // ---- edges ----
    EdgeAll EA;
    EA.ei[0] = (const int*)d_in[4]; EA.E[0] = in_sizes[4] / 2; EA.hsrc[0] = h_org; EA.hdst[0] = h_ind; // org->ind
    EA.ei[1] = (const int*)d_in[5]; EA.E[1] = in_sizes[5] / 2; EA.hsrc[1] = h_ext; EA.hdst[1] = h_ind; // ext->ind
    EA.ei[2] = (const int*)d_in[3]; EA.E[2] = in_sizes[3] / 2; EA.hsrc[2] = h_ind; EA.hdst[2] = h_org; // ind->org
    EA.ei[3] = (const int*)d_in[6]; EA.E[3] = in_sizes[6] / 2; EA.hsrc[3] = h_ext; EA.hdst[3] = h_org; // ext->org
    int Emax = 0;
    for (int t = 0; t < 4; t++) {
        EA.den[t]  = p_den + (size_t)t * N_NODES;
        EA.out[t]  = p_out + (size_t)t * N_NODES * HDIM;
        if (EA.E[t] > Emax) Emax = EA.E[t];
    }
    dim3 eg((Emax / 4 + 255) / 256 + 1, 4);
    edge_kernel<<<eg, 256>>>(EA);

    // ---- semantic attention (emits per-node A too) + tiny final ----
    const int NG = (N_NODES + 255) / 256;
    dim3 sg(NG, 4);
    score_kernel<<<sg, 256>>>(p_out, p_den, p_score);

    final_kernel<<<NG, 256>>>(p_score, (float*)d_out);
}